// round 16
// baseline (speedup 1.0000x reference)
#include <cuda_runtime.h>
#include <math.h>
#include <stdint.h>

#define Bb 8
#define Ll 512
#define Dd 1024
#define Hh 16
#define DKk 64
#define DVv 64
#define EPSF 1e-20f

#define BH (Bb*Hh)           // 128
#define NPOS (Bb*Hh*Ll)      // 65536
#define MROWS (Bb*Ll)        // 4096

// ---------------- scratch ----------------
__device__ float g_q[NPOS*DKk];
__device__ float g_k[NPOS*DKk];
__device__ float g_v[NPOS*DVv];
__device__ float g_S[(size_t)BH*Ll*Ll];
__device__ float g_ao[MROWS*Dd];
__device__ float g_pp[(size_t)32*NPOS];
__device__ float g_alpha[NPOS];
__device__ double g_kl;
__device__ float g_wt[4*Dd*Dd];          // W^T for Wq,Wk,Wv,Wo
__device__ float g_wtp[DKk*Dd];          // Wp1^T [1024,64]

// ---------------- helpers ----------------
__device__ __forceinline__ void mma_bf16(float* c, const uint32_t* a, const uint32_t* b) {
    asm volatile(
        "mma.sync.aligned.m16n8k16.row.col.f32.bf16.bf16.f32 "
        "{%0,%1,%2,%3}, {%4,%5,%6,%7}, {%8,%9}, {%0,%1,%2,%3};"
        : "+f"(c[0]), "+f"(c[1]), "+f"(c[2]), "+f"(c[3])
        : "r"(a[0]), "r"(a[1]), "r"(a[2]), "r"(a[3]), "r"(b[0]), "r"(b[1]));
}

// bf16 pair split: pack (x0,x1) hi-bf16s into hi, residual-bf16s into lo
__device__ __forceinline__ void splitpair(float x0, float x1, uint32_t& hi, uint32_t& lo) {
    uint32_t b0 = __float_as_uint(x0), b1 = __float_as_uint(x1);
    hi = __byte_perm(b0, b1, 0x7632);
    float l0 = x0 - __uint_as_float(b0 & 0xFFFF0000u);
    float l1 = x1 - __uint_as_float(b1 & 0xFFFF0000u);
    lo = __byte_perm(__float_as_uint(l0), __float_as_uint(l1), 0x7632);
}

__device__ __forceinline__ void cp16(uint32_t s, const void* g) {
    asm volatile("cp.async.ca.shared.global [%0], [%1], 16;" :: "r"(s), "l"(g));
}
#define CP_COMMIT() asm volatile("cp.async.commit_group;" ::: "memory")
#define CP_WAIT1()  asm volatile("cp.async.wait_group 1;" ::: "memory")
#define CP_WAIT3()  asm volatile("cp.async.wait_group 3;" ::: "memory")

// batched 32x32-tiled transposes of the 4 big weights [1024,1024]
__global__ void transpose4(const float* __restrict__ W0, const float* __restrict__ W1,
                           const float* __restrict__ W2, const float* __restrict__ W3) {
    __shared__ float t[32][33];
    int z = blockIdx.z;
    const float* W = (z == 0) ? W0 : (z == 1) ? W1 : (z == 2) ? W2 : W3;
    float* T = g_wt + (size_t)z * Dd * Dd;
    int bx = blockIdx.x * 32, by = blockIdx.y * 32;
    int tx = threadIdx.x, ty = threadIdx.y;
    #pragma unroll
    for (int j = 0; j < 4; j++)
        t[ty + 8 * j][tx] = W[(size_t)(by + ty + 8 * j) * 1024 + bx + tx];
    __syncthreads();
    #pragma unroll
    for (int j = 0; j < 4; j++)
        T[(size_t)(bx + ty + 8 * j) * 1024 + by + tx] = t[tx][ty + 8 * j];
}

__global__ void transpose_p(const float* __restrict__ W) {
    __shared__ float t[32][33];
    int bx = blockIdx.x * 32, by = blockIdx.y * 32;
    int tx = threadIdx.x, ty = threadIdx.y;
    #pragma unroll
    for (int j = 0; j < 4; j++)
        t[ty + 8 * j][tx] = W[(size_t)(by + ty + 8 * j) * 1024 + bx + tx];
    __syncthreads();
    #pragma unroll
    for (int j = 0; j < 4; j++)
        g_wtp[(size_t)(bx + ty + 8 * j) * 64 + by + tx] = t[tx][ty + 8 * j];
}

// ---------------- bf16x3 GEMM core, cp.async 5-stage ring (K=1024) ----------------
#define KB 16
#define KSTR 20
#define MATF 2560
#define STAGEF 5120
#define NPIPE 5

__device__ __forceinline__ void gemm_core(const float* A, const float* Bt,
                                          const float* bias, float* C,
                                          int scatter, float scale, float* sm) {
    int tid = threadIdx.x;
    int lane = tid & 31, wid = tid >> 5;
    int g = lane >> 2, t4 = lane & 3;
    int warp_m = wid & 1;
    int warp_n = wid >> 1;
    int row0 = blockIdx.y * 128;
    int col0 = blockIdx.x * 128;

    float acc[4][4][4];
    #pragma unroll
    for (int mt = 0; mt < 4; mt++)
        #pragma unroll
        for (int nt = 0; nt < 4; nt++)
            #pragma unroll
            for (int q = 0; q < 4; q++) acc[mt][nt][q] = 0.f;

    int r0i = tid >> 2, s0i = tid & 3;
    const float* pA0 = A  + (size_t)(row0 + r0i) * 1024 + s0i * 4;
    const float* pA1 = A  + (size_t)(row0 + 64 + r0i) * 1024 + s0i * 4;
    const float* pB0 = Bt + (size_t)(col0 + r0i) * 1024 + s0i * 4;
    const float* pB1 = Bt + (size_t)(col0 + 64 + r0i) * 1024 + s0i * 4;
    uint32_t smb = (uint32_t)__cvta_generic_to_shared(sm);
    uint32_t ad0 = smb + (r0i * KSTR + s0i * 4) * 4;
    uint32_t ad1 = smb + ((r0i + 64) * KSTR + s0i * 4) * 4;

    const int NSTAGE = 1024 / KB;      // 64

    #pragma unroll
    for (int st = 0; st < 4; st++) {
        uint32_t b = (uint32_t)(st * STAGEF * 4);
        int k0 = st * KB;
        cp16(ad0 + b, pA0 + k0);
        cp16(ad1 + b, pA1 + k0);
        cp16(ad0 + b + MATF * 4, pB0 + k0);
        cp16(ad1 + b + MATF * 4, pB1 + k0);
        CP_COMMIT();
    }

    for (int ks = 0; ks < NSTAGE; ks++) {
        CP_WAIT3();
        __syncthreads();
        int buf = ks % NPIPE;
        const float* Asmp = sm + buf * STAGEF + warp_m * 64 * KSTR;
        const float* Bsmp = sm + buf * STAGEF + MATF + warp_n * 32 * KSTR;

        {
            uint32_t bhf[4][2], blf[4][2];
            #pragma unroll
            for (int nt = 0; nt < 4; nt++) {
                const float* bp = Bsmp + (nt * 8 + g) * KSTR + 2 * t4;
                float2 p0 = *(const float2*)bp;
                float2 p1 = *(const float2*)(bp + 8);
                splitpair(p0.x, p0.y, bhf[nt][0], blf[nt][0]);
                splitpair(p1.x, p1.y, bhf[nt][1], blf[nt][1]);
            }
            #pragma unroll
            for (int mt = 0; mt < 4; mt++) {
                const float* ap = Asmp + (mt * 16 + g) * KSTR + 2 * t4;
                float2 q0 = *(const float2*)ap;
                float2 q1 = *(const float2*)(ap + 8 * KSTR);
                float2 q2 = *(const float2*)(ap + 8);
                float2 q3 = *(const float2*)(ap + 8 * KSTR + 8);
                uint32_t ah[4], al[4];
                splitpair(q0.x, q0.y, ah[0], al[0]);
                splitpair(q1.x, q1.y, ah[1], al[1]);
                splitpair(q2.x, q2.y, ah[2], al[2]);
                splitpair(q3.x, q3.y, ah[3], al[3]);
                #pragma unroll
                for (int nt = 0; nt < 4; nt++) mma_bf16(acc[mt][nt], ah, bhf[nt]);
                #pragma unroll
                for (int nt = 0; nt < 4; nt++) mma_bf16(acc[mt][nt], ah, blf[nt]);
                #pragma unroll
                for (int nt = 0; nt < 4; nt++) mma_bf16(acc[mt][nt], al, bhf[nt]);
            }
        }

        int ns = ks + 4;
        if (ns < NSTAGE) {
            uint32_t b = (uint32_t)((ns % NPIPE) * STAGEF * 4);
            int k0 = ns * KB;
            cp16(ad0 + b, pA0 + k0);
            cp16(ad1 + b, pA1 + k0);
            cp16(ad0 + b + MATF * 4, pB0 + k0);
            cp16(ad1 + b + MATF * 4, pB1 + k0);
        }
        CP_COMMIT();
    }

    #pragma unroll
    for (int mt = 0; mt < 4; mt++) {
        int r0r = row0 + warp_m * 64 + mt * 16 + g;
        int r1r = r0r + 8;
        #pragma unroll
        for (int nt = 0; nt < 4; nt++) {
            int c = col0 + warp_n * 32 + nt * 8 + 2 * t4;
            float b0 = __ldg(bias + c), b1 = __ldg(bias + c + 1);
            float2 v0 = make_float2((acc[mt][nt][0] + b0) * scale,
                                    (acc[mt][nt][1] + b1) * scale);
            float2 v1 = make_float2((acc[mt][nt][2] + b0) * scale,
                                    (acc[mt][nt][3] + b1) * scale);
            if (scatter) {
                int h_ = c >> 6, d_ = c & 63;
                int b0_ = r0r >> 9, l0_ = r0r & 511;
                int b1_ = r1r >> 9, l1_ = r1r & 511;
                *(float2*)(C + (((size_t)(b0_ * Hh + h_) * Ll) + l0_) * 64 + d_) = v0;
                *(float2*)(C + (((size_t)(b1_ * Hh + h_) * Ll) + l1_) * 64 + d_) = v1;
            } else {
                *(float2*)(C + (size_t)r0r * 1024 + c) = v0;
                *(float2*)(C + (size_t)r1r * 1024 + c) = v1;
            }
        }
    }
}

// merged Q/K/V projections, bf16x3
__global__ __launch_bounds__(256, 2) void qkv_mma(const float* __restrict__ Aq,
                                                  const float* __restrict__ Ak,
                                                  const float* __restrict__ Av,
                                                  const float* __restrict__ bq,
                                                  const float* __restrict__ bk,
                                                  const float* __restrict__ bv,
                                                  float* __restrict__ Cq,
                                                  float* __restrict__ Ck,
                                                  float* __restrict__ Cv) {
    extern __shared__ float sm[];
    int z = blockIdx.z;
    const float* A    = (z == 0) ? Aq : (z == 1) ? Ak : Av;
    const float* bias = (z == 0) ? bq : (z == 1) ? bk : bv;
    float* C          = (z == 0) ? Cq : (z == 1) ? Ck : Cv;
    gemm_core(A, g_wt + (size_t)z * Dd * Dd, bias, C, 1, (z == 0) ? 8.0f : 1.0f, sm);
}

__global__ __launch_bounds__(256, 2) void out_mma(const float* __restrict__ bias,
                                                  float* __restrict__ C) {
    extern __shared__ float sm[];
    gemm_core(g_ao, g_wt + (size_t)3 * Dd * Dd, bias, C, 0, 1.0f, sm);
}

// ---------------- bf16x3 batched QK^T (double-buffered, K=64) ----------------
#define DSTAGEF 5120
__global__ __launch_bounds__(256, 2) void score_mma() {
    extern __shared__ float sm[];
    int bh = blockIdx.z;
    const float* A  = g_q + (size_t)bh * Ll * DKk;
    const float* Bt = g_k + (size_t)bh * Ll * DKk;
    float* Sp = g_S + (size_t)bh * Ll * Ll;
    int tid = threadIdx.x;
    int lane = tid & 31, wid = tid >> 5;
    int g = lane >> 2, t4 = lane & 3;
    int warp_m = wid & 1;
    int warp_n = wid >> 1;
    int row0 = blockIdx.y * 128;
    int col0 = blockIdx.x * 128;

    float acc[4][4][4];
    #pragma unroll
    for (int mt = 0; mt < 4; mt++)
        #pragma unroll
        for (int nt = 0; nt < 4; nt++)
            #pragma unroll
            for (int q = 0; q < 4; q++) acc[mt][nt][q] = 0.f;

    int r0i = tid >> 2, s0i = tid & 3;
    const float* pA0 = A  + (size_t)(row0 + r0i) * 64 + s0i * 4;
    const float* pA1 = A  + (size_t)(row0 + 64 + r0i) * 64 + s0i * 4;
    const float* pB0 = Bt + (size_t)(col0 + r0i) * 64 + s0i * 4;
    const float* pB1 = Bt + (size_t)(col0 + 64 + r0i) * 64 + s0i * 4;
    int so0 = r0i * KSTR + s0i * 4;
    int so1 = (r0i + 64) * KSTR + s0i * 4;

    *(float4*)(sm + so0)         = *(const float4*)(pA0);
    *(float4*)(sm + so1)         = *(const float4*)(pA1);
    *(float4*)(sm + MATF + so0)  = *(const float4*)(pB0);
    *(float4*)(sm + MATF + so1)  = *(const float4*)(pB1);
    __syncthreads();

    const int NSTAGE = 64 / KB;    // 4
    for (int ks = 0; ks < NSTAGE; ks++) {
        int buf = ks & 1;
        float4 va0, va1, vb0, vb1;
        bool more = (ks + 1 < NSTAGE);
        if (more) {
            int k0 = (ks + 1) * KB;
            va0 = *(const float4*)(pA0 + k0);
            va1 = *(const float4*)(pA1 + k0);
            vb0 = *(const float4*)(pB0 + k0);
            vb1 = *(const float4*)(pB1 + k0);
        }

        const float* Asmp = sm + buf * DSTAGEF + warp_m * 64 * KSTR;
        const float* Bsmp = sm + buf * DSTAGEF + MATF + warp_n * 32 * KSTR;

        {
            uint32_t bhf[4][2], blf[4][2];
            #pragma unroll
            for (int nt = 0; nt < 4; nt++) {
                const float* bp = Bsmp + (nt * 8 + g) * KSTR + 2 * t4;
                float2 p0 = *(const float2*)bp;
                float2 p1 = *(const float2*)(bp + 8);
                splitpair(p0.x, p0.y, bhf[nt][0], blf[nt][0]);
                splitpair(p1.x, p1.y, bhf[nt][1], blf[nt][1]);
            }
            #pragma unroll
            for (int mt = 0; mt < 4; mt++) {
                const float* ap = Asmp + (mt * 16 + g) * KSTR + 2 * t4;
                float2 q0 = *(const float2*)ap;
                float2 q1 = *(const float2*)(ap + 8 * KSTR);
                float2 q2 = *(const float2*)(ap + 8);
                float2 q3 = *(const float2*)(ap + 8 * KSTR + 8);
                uint32_t ah[4], al[4];
                splitpair(q0.x, q0.y, ah[0], al[0]);
                splitpair(q1.x, q1.y, ah[1], al[1]);
                splitpair(q2.x, q2.y, ah[2], al[2]);
                splitpair(q3.x, q3.y, ah[3], al[3]);
                #pragma unroll
                for (int nt = 0; nt < 4; nt++) mma_bf16(acc[mt][nt], ah, bhf[nt]);
                #pragma unroll
                for (int nt = 0; nt < 4; nt++) mma_bf16(acc[mt][nt], ah, blf[nt]);
                #pragma unroll
                for (int nt = 0; nt < 4; nt++) mma_bf16(acc[mt][nt], al, bhf[nt]);
            }
        }

        if (more) {
            float* nb = sm + ((ks + 1) & 1) * DSTAGEF;
            __syncthreads();
            *(float4*)(nb + so0)        = va0;
            *(float4*)(nb + so1)        = va1;
            *(float4*)(nb + MATF + so0) = vb0;
            *(float4*)(nb + MATF + so1) = vb1;
            __syncthreads();
        }
    }

    #pragma unroll
    for (int mt = 0; mt < 4; mt++) {
        int r0r = row0 + warp_m * 64 + mt * 16 + g;
        int r1r = r0r + 8;
        #pragma unroll
        for (int nt = 0; nt < 4; nt++) {
            int c = col0 + warp_n * 32 + nt * 8 + 2 * t4;
            *(float2*)(Sp + (size_t)r0r * 512 + c) = make_float2(acc[mt][nt][0], acc[mt][nt][1]);
            *(float2*)(Sp + (size_t)r1r * 512 + c) = make_float2(acc[mt][nt][2], acc[mt][nt][3]);
        }
    }
}

// ---------------- bf16x3 prior MLP (double-buffered, K=64) ----------------
__global__ __launch_bounds__(256, 2) void prior_mma(const float* __restrict__ bp1,
                                                    const float* __restrict__ Wp2)
{
    extern __shared__ float sm[];
    const float* A = g_k;
    const float* Bt = g_wtp;
    int tid = threadIdx.x;
    int lane = tid & 31, wid = tid >> 5;
    int g = lane >> 2, t4 = lane & 3;
    int warp_m = wid & 1;
    int warp_n = wid >> 1;
    int row0 = blockIdx.y * 128;
    int col0 = blockIdx.x * 128;

    float acc[4][4][4];
    #pragma unroll
    for (int mt = 0; mt < 4; mt++)
        #pragma unroll
        for (int nt = 0; nt < 4; nt++)
            #pragma unroll
            for (int q = 0; q < 4; q++) acc[mt][nt][q] = 0.f;

    int r0i = tid >> 2, s0i = tid & 3;
    const float* pA0 = A  + (size_t)(row0 + r0i) * 64 + s0i * 4;
    const float* pA1 = A  + (size_t)(row0 + 64 + r0i) * 64 + s0i * 4;
    const float* pB0 = Bt + (size_t)(col0 + r0i) * 64 + s0i * 4;
    const float* pB1 = Bt + (size_t)(col0 + 64 + r0i) * 64 + s0i * 4;
    int so0 = r0i * KSTR + s0i * 4;
    int so1 = (r0i + 64) * KSTR + s0i * 4;

    *(float4*)(sm + so0)         = *(const float4*)(pA0);
    *(float4*)(sm + so1)         = *(const float4*)(pA1);
    *(float4*)(sm + MATF + so0)  = *(const float4*)(pB0);
    *(float4*)(sm + MATF + so1)  = *(const float4*)(pB1);
    __syncthreads();

    const int NSTAGE = 64 / KB;    // 4
    for (int ks = 0; ks < NSTAGE; ks++) {
        int buf = ks & 1;
        float4 va0, va1, vb0, vb1;
        bool more = (ks + 1 < NSTAGE);
        if (more) {
            int k0 = (ks + 1) * KB;
            va0 = *(const float4*)(pA0 + k0);
            va1 = *(const float4*)(pA1 + k0);
            vb0 = *(const float4*)(pB0 + k0);
            vb1 = *(const float4*)(pB1 + k0);
        }

        const float* Asmp = sm + buf * DSTAGEF + warp_m * 64 * KSTR;
        const float* Bsmp = sm + buf * DSTAGEF + MATF + warp_n * 32 * KSTR;

        {
            uint32_t bhf[4][2], blf[4][2];
            #pragma unroll
            for (int nt = 0; nt < 4; nt++) {
                const float* bp = Bsmp + (nt * 8 + g) * KSTR + 2 * t4;
                float2 p0 = *(const float2*)bp;
                float2 p1 = *(const float2*)(bp + 8);
                splitpair(p0.x, p0.y, bhf[nt][0], blf[nt][0]);
                splitpair(p1.x, p1.y, bhf[nt][1], blf[nt][1]);
            }
            #pragma unroll
            for (int mt = 0; mt < 4; mt++) {
                const float* ap = Asmp + (mt * 16 + g) * KSTR + 2 * t4;
                float2 q0 = *(const float2*)ap;
                float2 q1 = *(const float2*)(ap + 8 * KSTR);
                float2 q2 = *(const float2*)(ap + 8);
                float2 q3 = *(const float2*)(ap + 8 * KSTR + 8);
                uint32_t ah[4], al[4];
                splitpair(q0.x, q0.y, ah[0], al[0]);
                splitpair(q1.x, q1.y, ah[1], al[1]);
                splitpair(q2.x, q2.y, ah[2], al[2]);
                splitpair(q3.x, q3.y, ah[3], al[3]);
                #pragma unroll
                for (int nt = 0; nt < 4; nt++) mma_bf16(acc[mt][nt], ah, bhf[nt]);
                #pragma unroll
                for (int nt = 0; nt < 4; nt++) mma_bf16(acc[mt][nt], ah, blf[nt]);
                #pragma unroll
                for (int nt = 0; nt < 4; nt++) mma_bf16(acc[mt][nt], al, bhf[nt]);
            }
        }

        if (more) {
            float* nb = sm + ((ks + 1) & 1) * DSTAGEF;
            __syncthreads();
            *(float4*)(nb + so0)        = va0;
            *(float4*)(nb + so1)        = va1;
            *(float4*)(nb + MATF + so0) = vb0;
            *(float4*)(nb + MATF + so1) = vb1;
            __syncthreads();
        }
    }

    size_t grp = (size_t)(blockIdx.x * 4 + warp_n) * NPOS;
    #pragma unroll
    for (int mt = 0; mt < 4; mt++) {
        float rs0 = 0.f, rs1 = 0.f;
        #pragma unroll
        for (int nt = 0; nt < 4; nt++) {
            int c = col0 + warp_n * 32 + nt * 8 + 2 * t4;
            float b0 = __ldg(bp1 + c), b1 = __ldg(bp1 + c + 1);
            float w0 = __ldg(Wp2 + c), w1 = __ldg(Wp2 + c + 1);
            float hv;
            hv = acc[mt][nt][0] + b0; hv = (hv >= 0.f) ? hv : 0.01f * hv; rs0 = fmaf(hv, w0, rs0);
            hv = acc[mt][nt][1] + b1; hv = (hv >= 0.f) ? hv : 0.01f * hv; rs0 = fmaf(hv, w1, rs0);
            hv = acc[mt][nt][2] + b0; hv = (hv >= 0.f) ? hv : 0.01f * hv; rs1 = fmaf(hv, w0, rs1);
            hv = acc[mt][nt][3] + b1; hv = (hv >= 0.f) ? hv : 0.01f * hv; rs1 = fmaf(hv, w1, rs1);
        }
        rs0 += __shfl_xor_sync(0xffffffffu, rs0, 1);
        rs0 += __shfl_xor_sync(0xffffffffu, rs0, 2);
        rs1 += __shfl_xor_sync(0xffffffffu, rs1, 1);
        rs1 += __shfl_xor_sync(0xffffffffu, rs1, 2);
        if (t4 == 0) {
            int r0r = row0 + warp_m * 64 + mt * 16 + g;
            g_pp[grp + r0r]     = rs0;
            g_pp[grp + r0r + 8] = rs1;
        }
    }
}

// ---------------- bf16x3 att_s @ V, cp.async 5-stage ----------------
#define VSTR 72
#define PAF 2560
#define PBF (16*VSTR)
#define PSTAGEF (PAF + PBF)
__global__ __launch_bounds__(256, 2) void pv_mma() {
    extern __shared__ float sm[];
    int bh = blockIdx.y;
    int b_ = bh >> 4, h_ = bh & 15;
    const float* A  = g_S + (size_t)bh * Ll * Ll;
    const float* Bv = g_v + (size_t)bh * Ll * DVv;
    int tid = threadIdx.x;
    int lane = tid & 31, wid = tid >> 5;
    int g = lane >> 2, t4 = lane & 3;
    int warp_m = wid & 3;
    int warp_n = wid >> 2;
    int row0 = blockIdx.x * 128;

    float acc[2][4][4];
    #pragma unroll
    for (int mt = 0; mt < 2; mt++)
        #pragma unroll
        for (int nt = 0; nt < 4; nt++)
            #pragma unroll
            for (int q = 0; q < 4; q++) acc[mt][nt][q] = 0.f;

    int r0i = tid >> 2, s0i = tid & 3;
    const float* pA0 = A + (size_t)(row0 + r0i) * 512 + s0i * 4;
    const float* pA1 = A + (size_t)(row0 + 64 + r0i) * 512 + s0i * 4;
    int rowb = tid >> 4, segb = tid & 15;
    const float* pBv = Bv + (size_t)rowb * 64 + segb * 4;
    uint32_t smb = (uint32_t)__cvta_generic_to_shared(sm);
    uint32_t ad0 = smb + (r0i * KSTR + s0i * 4) * 4;
    uint32_t ad1 = smb + ((r0i + 64) * KSTR + s0i * 4) * 4;
    uint32_t adb = smb + (PAF + rowb * VSTR + segb * 4) * 4;

    const int NSTAGE = 512 / KB;   // 32

    #pragma unroll
    for (int st = 0; st < 4; st++) {
        uint32_t b = (uint32_t)(st * PSTAGEF * 4);
        int k0 = st * KB;
        cp16(ad0 + b, pA0 + k0);
        cp16(ad1 + b, pA1 + k0);
        cp16(adb + b, pBv + (size_t)k0 * 64);
        CP_COMMIT();
    }

    for (int ks = 0; ks < NSTAGE; ks++) {
        CP_WAIT3();
        __syncthreads();
        int buf = ks % NPIPE;
        const float* Asmp = sm + buf * PSTAGEF + warp_m * 32 * KSTR;
        const float* Bsmp = sm + buf * PSTAGEF + PAF;

        {
            uint32_t bhf[4][2], blf[4][2];
            #pragma unroll
            for (int nt = 0; nt < 4; nt++) {
                int col = warp_n * 32 + nt * 8 + g;
                float b00 = Bsmp[(2 * t4) * VSTR + col];
                float b01 = Bsmp[(2 * t4 + 1) * VSTR + col];
                float b10 = Bsmp[(2 * t4 + 8) * VSTR + col];
                float b11 = Bsmp[(2 * t4 + 9) * VSTR + col];
                splitpair(b00, b01, bhf[nt][0], blf[nt][0]);
                splitpair(b10, b11, bhf[nt][1], blf[nt][1]);
            }
            #pragma unroll
            for (int mt = 0; mt < 2; mt++) {
                const float* ap = Asmp + (mt * 16 + g) * KSTR + 2 * t4;
                float2 q0 = *(const float2*)ap;
                float2 q1 = *(const float2*)(ap + 8 * KSTR);
                float2 q2 = *(const float2*)(ap + 8);
                float2 q3 = *(const float2*)(ap + 8 * KSTR + 8);
                uint32_t ah[4], al[4];
                splitpair(q0.x, q0.y, ah[0], al[0]);
                splitpair(q1.x, q1.y, ah[1], al[1]);
                splitpair(q2.x, q2.y, ah[2], al[2]);
                splitpair(q3.x, q3.y, ah[3], al[3]);
                #pragma unroll
                for (int nt = 0; nt < 4; nt++) mma_bf16(acc[mt][nt], ah, bhf[nt]);
                #pragma unroll
                for (int nt = 0; nt < 4; nt++) mma_bf16(acc[mt][nt], ah, blf[nt]);
                #pragma unroll
                for (int nt = 0; nt < 4; nt++) mma_bf16(acc[mt][nt], al, bhf[nt]);
            }
        }

        int ns = ks + 4;
        if (ns < NSTAGE) {
            uint32_t b = (uint32_t)((ns % NPIPE) * PSTAGEF * 4);
            int k0 = ns * KB;
            cp16(ad0 + b, pA0 + k0);
            cp16(ad1 + b, pA1 + k0);
            cp16(adb + b, pBv + (size_t)k0 * 64);
        }
        CP_COMMIT();
    }

    #pragma unroll
    for (int mt = 0; mt < 2; mt++) {
        int r0r = row0 + warp_m * 32 + mt * 16 + g;
        int r1r = r0r + 8;
        #pragma unroll
        for (int nt = 0; nt < 4; nt++) {
            int c = warp_n * 32 + nt * 8 + 2 * t4;
            *(float2*)(g_ao + ((size_t)b_ * Ll + r0r) * Dd + h_ * DVv + c) =
                make_float2(acc[mt][nt][0], acc[mt][nt][1]);
            *(float2*)(g_ao + ((size_t)b_ * Ll + r1r) * Dd + h_ * DVv + c) =
                make_float2(acc[mt][nt][2], acc[mt][nt][3]);
        }
    }
}

// ---------------- block reduction helper ----------------
__device__ __forceinline__ float blkred(float v, bool ismax, float* sred) {
    #pragma unroll
    for (int o = 16; o; o >>= 1) {
        float w = __shfl_xor_sync(0xffffffffu, v, o);
        v = ismax ? fmaxf(v, w) : v + w;
    }
    int wid = threadIdx.x >> 5, lid = threadIdx.x & 31;
    int nw = blockDim.x >> 5;
    if (lid == 0) sred[wid] = v;
    __syncthreads();
    if (wid == 0) {
        v = (lid < nw) ? sred[lid] : (ismax ? -3.402823e38f : 0.f);
        #pragma unroll
        for (int o = 16; o; o >>= 1) {
            float w = __shfl_xor_sync(0xffffffffu, v, o);
            v = ismax ? fmaxf(v, w) : v + w;
        }
        if (lid == 0) sred[0] = v;
    }
    __syncthreads();
    float r = sred[0];
    __syncthreads();
    return r;
}

// ---------------- fast branchless lgamma ----------------
__device__ __forceinline__ float lgamma_fast(float x) {
    bool refl = (x < 0.5f);
    float z = refl ? 1.0f - x : x;
    float p = 1.0f;
    #pragma unroll
    for (int i = 0; i < 8; i++) {
        if (z < 8.0f) { p *= z; z += 1.0f; }
    }
    float invz  = 1.0f / z;
    float invz2 = invz * invz;
    float lz = __logf(z);
    float lg = (z - 0.5f) * lz - z + 0.91893853320467274f
             + invz * (8.3333333333e-2f
             + invz2 * (-2.7777777778e-3f + 7.9365079365e-4f * invz2));
    lg -= __logf(p);
    if (refl) {
        float s = sinpif(x);
        lg = 1.1447298858494002f - __logf(fabsf(s)) - lg;
    }
    return lg;
}

// ---------------- alpha: fused 32-partial reduce + softmax + KL const terms ----------------
__global__ __launch_bounds__(512) void alpha_kernel(const float* __restrict__ bp2) {
    __shared__ float sred[32];
    int bh = blockIdx.x;
    int t = threadIdx.x;
    int i = bh * Ll + t;
    float x = 0.f;
    #pragma unroll
    for (int g2 = 0; g2 < 32; g2++) x += g_pp[(size_t)g2 * NPOS + i];
    x += bp2[0];
    float m = blkred(x, true, sred);
    float e = expf(x - m);
    float den = blkred(e, false, sred);
    float a = e / den;
    g_alpha[i] = a;
    const float lg1 = 0.69314718f;
    const float EG  = 0.5772156649f;
    float C = a * lg1 + 2.f * EG * a + lgammaf(a + EPSF);
    float sc = blkred(C, false, sred);
    if (t == 0) atomicAdd(&g_kl, (double)(512.0f * sc));
}

// ---------------- fused row pass: warp per row ----------------
__global__ __launch_bounds__(256) void row_fused(const float* __restrict__ U) {
    int lane = threadIdx.x & 31;
    int wrp = threadIdx.x >> 5;
    int row = blockIdx.x * 8 + wrp;
    int bh = row >> 9;
    size_t base = (size_t)row * 512;

    float s[16];
    float m = -3.402823e38f;
    #pragma unroll
    for (int i = 0; i < 16; i++) {
        s[i] = g_S[base + lane + 32 * i];
        m = fmaxf(m, s[i]);
    }
    #pragma unroll
    for (int o = 16; o; o >>= 1) m = fmaxf(m, __shfl_xor_sync(0xffffffffu, m, o));

    float den = 0.f;
    #pragma unroll
    for (int i = 0; i < 16; i++) den += __expf(s[i] - m);
    #pragma unroll
    for (int o = 16; o; o >>= 1) den += __shfl_xor_sync(0xffffffffu, den, o);
    float logden = __logf(den);

    float t[16];
    float kl = 0.f;
    #pragma unroll
    for (int i = 0; i < 16; i++) {
        float r = s[i] - m - logden;
        float p = __expf(r);
        float lp = (r > -41.4f) ? r : __logf(p + EPSF);
        float a = g_alpha[bh * 512 + lane + 32 * i];
        kl += fmaf(-a, lp, p);
        float u = U[base + lane + 32 * i];
        float ws = u * (1.f + u * (0.5f + 0.33333333f * u));
        float wl = -__logf(1.f - u + EPSF);
        float w = (u < 0.015f) ? ws : wl;
        float gw = __logf(w + EPSF);
        t[i] = lp - lgamma_fast(3.f + 2.f * gw);
    }

    float m2 = -3.402823e38f;
    #pragma unroll
    for (int i = 0; i < 16; i++) m2 = fmaxf(m2, t[i]);
    #pragma unroll
    for (int o = 16; o; o >>= 1) m2 = fmaxf(m2, __shfl_xor_sync(0xffffffffu, m2, o));

    float d2 = 0.f;
    #pragma unroll
    for (int i = 0; i < 16; i++) d2 += __expf(t[i] - m2);
    #pragma unroll
    for (int o = 16; o; o >>= 1) d2 += __shfl_xor_sync(0xffffffffu, d2, o);
    float i2 = 1.f / d2;

    #pragma unroll
    for (int i = 0; i < 16; i++)
        g_S[base + lane + 32 * i] = __expf(t[i] - m2) * i2;

    #pragma unroll
    for (int o = 16; o; o >>= 1) kl += __shfl_xor_sync(0xffffffffu, kl, o);
    if (lane == 0) atomicAdd(&g_kl, (double)kl);
}

// ---------------- misc ----------------
__global__ void zero_kernel() { g_kl = 0.0; }

__global__ void finalize_kernel(float* out, int out_size) {
    if (out_size > Bb * Ll * Dd)
        out[Bb * Ll * Dd] = (float)(g_kl / 33554432.0);
}

// ---------------- launch ----------------
extern "C" void kernel_launch(void* const* d_in, const int* in_sizes, int n_in,
                              void* d_out, int out_size) {
    const float* queries = (const float*)d_in[0];
    const float* keys    = (const float*)d_in[1];
    const float* values  = (const float*)d_in[2];
    const float* unif    = (const float*)d_in[3];
    const float* Wq = (const float*)d_in[4];
    const float* bq = (const float*)d_in[5];
    const float* Wk = (const float*)d_in[6];
    const float* bk = (const float*)d_in[7];
    const float* Wv = (const float*)d_in[8];
    const float* bv = (const float*)d_in[9];
    const float* Wo = (const float*)d_in[10];
    const float* bo = (const float*)d_in[11];
    const float* Wp1 = (const float*)d_in[12];
    const float* bp1 = (const float*)d_in[13];
    const float* Wp2 = (const float*)d_in[14];
    const float* bp2 = (const float*)d_in[15];
    float* out = (float*)d_out;

    float *pq, *pk, *pv_;
    cudaGetSymbolAddress((void**)&pq, g_q);
    cudaGetSymbolAddress((void**)&pk, g_k);
    cudaGetSymbolAddress((void**)&pv_, g_v);

    const int GSMEM  = NPIPE * STAGEF * 4;    // 102400 B
    const int DBSMEM = 2 * DSTAGEF * 4;       // 40960 B
    const int PSMEM  = NPIPE * PSTAGEF * 4;   // 74240 B
    static int init_done = 0;
    static cudaStream_t s_aux;
    static cudaEvent_t ev_fork0, ev_p, ev_fork, ev_join;
    if (!init_done) {
        cudaFuncSetAttribute(qkv_mma, cudaFuncAttributeMaxDynamicSharedMemorySize, GSMEM);
        cudaFuncSetAttribute(out_mma, cudaFuncAttributeMaxDynamicSharedMemorySize, GSMEM);
        cudaFuncSetAttribute(score_mma, cudaFuncAttributeMaxDynamicSharedMemorySize, DBSMEM);
        cudaFuncSetAttribute(prior_mma, cudaFuncAttributeMaxDynamicSharedMemorySize, DBSMEM);
        cudaFuncSetAttribute(pv_mma, cudaFuncAttributeMaxDynamicSharedMemorySize, PSMEM);
        cudaStreamCreateWithFlags(&s_aux, cudaStreamNonBlocking);
        cudaEventCreateWithFlags(&ev_fork0, cudaEventDisableTiming);
        cudaEventCreateWithFlags(&ev_p, cudaEventDisableTiming);
        cudaEventCreateWithFlags(&ev_fork, cudaEventDisableTiming);
        cudaEventCreateWithFlags(&ev_join, cudaEventDisableTiming);
        init_done = 1;
    }

    zero_kernel<<<1, 1>>>();

    dim3 tr(32, 8);
    // transpose_p overlapped on aux stream (only needed before prior_mma)
    cudaEventRecord(ev_fork0, 0);
    cudaStreamWaitEvent(s_aux, ev_fork0, 0);
    transpose_p<<<dim3(32, 2), tr, 0, s_aux>>>(Wp1);
    cudaEventRecord(ev_p, s_aux);

    transpose4<<<dim3(32, 32, 4), tr>>>(Wq, Wk, Wv, Wo);
    qkv_mma<<<dim3(8, 32, 3), 256, GSMEM>>>(queries, keys, values, bq, bk, bv, pq, pk, pv_);

    // fork: score on aux stream, prior chain on main stream (independent)
    cudaEventRecord(ev_fork, 0);
    cudaStreamWaitEvent(s_aux, ev_fork, 0);
    score_mma<<<dim3(4, 4, BH), 256, DBSMEM, s_aux>>>();
    cudaEventRecord(ev_join, s_aux);

    cudaStreamWaitEvent(0, ev_p, 0);
    prior_mma<<<dim3(8, 512), 256, DBSMEM>>>(bp1, Wp2);
    alpha_kernel<<<BH, 512>>>(bp2);

    cudaStreamWaitEvent(0, ev_join, 0);

    row_fused<<<NPOS / 8, 256>>>(unif);
    pv_mma<<<dim3(4, BH), 256, PSMEM>>>();

    out_mma<<<dim3(8, 32), 256, GSMEM>>>(bo, out);

    finalize_kernel<<<1, 1>>>(out, out_size);
}

// round 17
// speedup vs baseline: 1.0434x; 1.0434x over previous
#include <cuda_runtime.h>
#include <math.h>
#include <stdint.h>

#define Bb 8
#define Ll 512
#define Dd 1024
#define Hh 16
#define DKk 64
#define DVv 64
#define EPSF 1e-20f

#define BH (Bb*Hh)           // 128
#define NPOS (Bb*Hh*Ll)      // 65536
#define MROWS (Bb*Ll)        // 4096

// ---------------- scratch ----------------
__device__ float g_q[NPOS*DKk];
__device__ float g_k[NPOS*DKk];
__device__ float g_v[NPOS*DVv];
__device__ float g_S[(size_t)BH*Ll*Ll];
__device__ float g_ao[MROWS*Dd];
__device__ float g_pp[(size_t)32*NPOS];
__device__ float g_alpha[NPOS];
__device__ double g_kl;
__device__ float g_wt[4*Dd*Dd];          // W^T for Wq,Wk,Wv,Wo
__device__ float g_wtp[DKk*Dd];          // Wp1^T [1024,64]

// ---------------- helpers ----------------
__device__ __forceinline__ void mma_bf16(float* c, const uint32_t* a, const uint32_t* b) {
    asm volatile(
        "mma.sync.aligned.m16n8k16.row.col.f32.bf16.bf16.f32 "
        "{%0,%1,%2,%3}, {%4,%5,%6,%7}, {%8,%9}, {%0,%1,%2,%3};"
        : "+f"(c[0]), "+f"(c[1]), "+f"(c[2]), "+f"(c[3])
        : "r"(a[0]), "r"(a[1]), "r"(a[2]), "r"(a[3]), "r"(b[0]), "r"(b[1]));
}

// bf16 pair split: pack (x0,x1) hi-bf16s into hi, residual-bf16s into lo
__device__ __forceinline__ void splitpair(float x0, float x1, uint32_t& hi, uint32_t& lo) {
    uint32_t b0 = __float_as_uint(x0), b1 = __float_as_uint(x1);
    hi = __byte_perm(b0, b1, 0x7632);
    float l0 = x0 - __uint_as_float(b0 & 0xFFFF0000u);
    float l1 = x1 - __uint_as_float(b1 & 0xFFFF0000u);
    lo = __byte_perm(__float_as_uint(l0), __float_as_uint(l1), 0x7632);
}

__device__ __forceinline__ void cp16(uint32_t s, const void* g) {
    asm volatile("cp.async.ca.shared.global [%0], [%1], 16;" :: "r"(s), "l"(g));
}
#define CP_COMMIT() asm volatile("cp.async.commit_group;" ::: "memory")
#define CP_WAIT1()  asm volatile("cp.async.wait_group 1;" ::: "memory")

// batched 32x32-tiled transposes of the 4 big weights [1024,1024]
__global__ void transpose4(const float* __restrict__ W0, const float* __restrict__ W1,
                           const float* __restrict__ W2, const float* __restrict__ W3) {
    __shared__ float t[32][33];
    int z = blockIdx.z;
    const float* W = (z == 0) ? W0 : (z == 1) ? W1 : (z == 2) ? W2 : W3;
    float* T = g_wt + (size_t)z * Dd * Dd;
    int bx = blockIdx.x * 32, by = blockIdx.y * 32;
    int tx = threadIdx.x, ty = threadIdx.y;
    #pragma unroll
    for (int j = 0; j < 4; j++)
        t[ty + 8 * j][tx] = W[(size_t)(by + ty + 8 * j) * 1024 + bx + tx];
    __syncthreads();
    #pragma unroll
    for (int j = 0; j < 4; j++)
        T[(size_t)(bx + ty + 8 * j) * 1024 + by + tx] = t[tx][ty + 8 * j];
}

__global__ void transpose_p(const float* __restrict__ W) {
    __shared__ float t[32][33];
    int bx = blockIdx.x * 32, by = blockIdx.y * 32;
    int tx = threadIdx.x, ty = threadIdx.y;
    #pragma unroll
    for (int j = 0; j < 4; j++)
        t[ty + 8 * j][tx] = W[(size_t)(by + ty + 8 * j) * 1024 + bx + tx];
    __syncthreads();
    #pragma unroll
    for (int j = 0; j < 4; j++)
        g_wtp[(size_t)(bx + ty + 8 * j) * 64 + by + tx] = t[tx][ty + 8 * j];
}

// ---------------- bf16x3 GEMM core, cp.async 3-stage ring (K=1024) ----------------
#define KB 16
#define KSTR 20
#define MATF 2560
#define STAGEF 5120
#define NPIPE 3

__device__ __forceinline__ void gemm_core(const float* A, const float* Bt,
                                          const float* bias, float* C,
                                          int scatter, float scale, float* sm) {
    int tid = threadIdx.x;
    int lane = tid & 31, wid = tid >> 5;
    int g = lane >> 2, t4 = lane & 3;
    int warp_m = wid & 1;
    int warp_n = wid >> 1;
    int row0 = blockIdx.y * 128;
    int col0 = blockIdx.x * 128;

    float acc[4][4][4];
    #pragma unroll
    for (int mt = 0; mt < 4; mt++)
        #pragma unroll
        for (int nt = 0; nt < 4; nt++)
            #pragma unroll
            for (int q = 0; q < 4; q++) acc[mt][nt][q] = 0.f;

    int r0i = tid >> 2, s0i = tid & 3;
    const float* pA0 = A  + (size_t)(row0 + r0i) * 1024 + s0i * 4;
    const float* pA1 = A  + (size_t)(row0 + 64 + r0i) * 1024 + s0i * 4;
    const float* pB0 = Bt + (size_t)(col0 + r0i) * 1024 + s0i * 4;
    const float* pB1 = Bt + (size_t)(col0 + 64 + r0i) * 1024 + s0i * 4;
    uint32_t smb = (uint32_t)__cvta_generic_to_shared(sm);
    uint32_t ad0 = smb + (r0i * KSTR + s0i * 4) * 4;
    uint32_t ad1 = smb + ((r0i + 64) * KSTR + s0i * 4) * 4;

    const int NSTAGE = 1024 / KB;      // 64

    #pragma unroll
    for (int st = 0; st < 2; st++) {
        uint32_t b = (uint32_t)(st * STAGEF * 4);
        int k0 = st * KB;
        cp16(ad0 + b, pA0 + k0);
        cp16(ad1 + b, pA1 + k0);
        cp16(ad0 + b + MATF * 4, pB0 + k0);
        cp16(ad1 + b + MATF * 4, pB1 + k0);
        CP_COMMIT();
    }

    for (int ks = 0; ks < NSTAGE; ks++) {
        CP_WAIT1();
        __syncthreads();
        int buf = ks % NPIPE;
        const float* Asmp = sm + buf * STAGEF + warp_m * 64 * KSTR;
        const float* Bsmp = sm + buf * STAGEF + MATF + warp_n * 32 * KSTR;

        {
            uint32_t bhf[4][2], blf[4][2];
            #pragma unroll
            for (int nt = 0; nt < 4; nt++) {
                const float* bp = Bsmp + (nt * 8 + g) * KSTR + 2 * t4;
                float2 p0 = *(const float2*)bp;
                float2 p1 = *(const float2*)(bp + 8);
                splitpair(p0.x, p0.y, bhf[nt][0], blf[nt][0]);
                splitpair(p1.x, p1.y, bhf[nt][1], blf[nt][1]);
            }
            #pragma unroll
            for (int mt = 0; mt < 4; mt++) {
                const float* ap = Asmp + (mt * 16 + g) * KSTR + 2 * t4;
                float2 q0 = *(const float2*)ap;
                float2 q1 = *(const float2*)(ap + 8 * KSTR);
                float2 q2 = *(const float2*)(ap + 8);
                float2 q3 = *(const float2*)(ap + 8 * KSTR + 8);
                uint32_t ah[4], al[4];
                splitpair(q0.x, q0.y, ah[0], al[0]);
                splitpair(q1.x, q1.y, ah[1], al[1]);
                splitpair(q2.x, q2.y, ah[2], al[2]);
                splitpair(q3.x, q3.y, ah[3], al[3]);
                #pragma unroll
                for (int nt = 0; nt < 4; nt++) mma_bf16(acc[mt][nt], ah, bhf[nt]);
                #pragma unroll
                for (int nt = 0; nt < 4; nt++) mma_bf16(acc[mt][nt], ah, blf[nt]);
                #pragma unroll
                for (int nt = 0; nt < 4; nt++) mma_bf16(acc[mt][nt], al, bhf[nt]);
            }
        }

        int ns = ks + 2;
        if (ns < NSTAGE) {
            uint32_t b = (uint32_t)((ns % NPIPE) * STAGEF * 4);
            int k0 = ns * KB;
            cp16(ad0 + b, pA0 + k0);
            cp16(ad1 + b, pA1 + k0);
            cp16(ad0 + b + MATF * 4, pB0 + k0);
            cp16(ad1 + b + MATF * 4, pB1 + k0);
        }
        CP_COMMIT();
    }

    #pragma unroll
    for (int mt = 0; mt < 4; mt++) {
        int r0r = row0 + warp_m * 64 + mt * 16 + g;
        int r1r = r0r + 8;
        #pragma unroll
        for (int nt = 0; nt < 4; nt++) {
            int c = col0 + warp_n * 32 + nt * 8 + 2 * t4;
            float b0 = __ldg(bias + c), b1 = __ldg(bias + c + 1);
            float2 v0 = make_float2((acc[mt][nt][0] + b0) * scale,
                                    (acc[mt][nt][1] + b1) * scale);
            float2 v1 = make_float2((acc[mt][nt][2] + b0) * scale,
                                    (acc[mt][nt][3] + b1) * scale);
            if (scatter) {
                int h_ = c >> 6, d_ = c & 63;
                int b0_ = r0r >> 9, l0_ = r0r & 511;
                int b1_ = r1r >> 9, l1_ = r1r & 511;
                *(float2*)(C + (((size_t)(b0_ * Hh + h_) * Ll) + l0_) * 64 + d_) = v0;
                *(float2*)(C + (((size_t)(b1_ * Hh + h_) * Ll) + l1_) * 64 + d_) = v1;
            } else {
                *(float2*)(C + (size_t)r0r * 1024 + c) = v0;
                *(float2*)(C + (size_t)r1r * 1024 + c) = v1;
            }
        }
    }
}

// merged Q/K/V projections, bf16x3
__global__ __launch_bounds__(256, 2) void qkv_mma(const float* __restrict__ Aq,
                                                  const float* __restrict__ Ak,
                                                  const float* __restrict__ Av,
                                                  const float* __restrict__ bq,
                                                  const float* __restrict__ bk,
                                                  const float* __restrict__ bv,
                                                  float* __restrict__ Cq,
                                                  float* __restrict__ Ck,
                                                  float* __restrict__ Cv) {
    extern __shared__ float sm[];
    int z = blockIdx.z;
    const float* A    = (z == 0) ? Aq : (z == 1) ? Ak : Av;
    const float* bias = (z == 0) ? bq : (z == 1) ? bk : bv;
    float* C          = (z == 0) ? Cq : (z == 1) ? Ck : Cv;
    gemm_core(A, g_wt + (size_t)z * Dd * Dd, bias, C, 1, (z == 0) ? 8.0f : 1.0f, sm);
}

__global__ __launch_bounds__(256, 2) void out_mma(const float* __restrict__ bias,
                                                  float* __restrict__ C) {
    extern __shared__ float sm[];
    gemm_core(g_ao, g_wt + (size_t)3 * Dd * Dd, bias, C, 0, 1.0f, sm);
}

// ---------------- bf16x3 batched QK^T (double-buffered, K=64) ----------------
__global__ __launch_bounds__(256, 2) void score_mma() {
    extern __shared__ float sm[];
    int bh = blockIdx.z;
    const float* A  = g_q + (size_t)bh * Ll * DKk;
    const float* Bt = g_k + (size_t)bh * Ll * DKk;
    float* Sp = g_S + (size_t)bh * Ll * Ll;
    int tid = threadIdx.x;
    int lane = tid & 31, wid = tid >> 5;
    int g = lane >> 2, t4 = lane & 3;
    int warp_m = wid & 1;
    int warp_n = wid >> 1;
    int row0 = blockIdx.y * 128;
    int col0 = blockIdx.x * 128;

    float acc[4][4][4];
    #pragma unroll
    for (int mt = 0; mt < 4; mt++)
        #pragma unroll
        for (int nt = 0; nt < 4; nt++)
            #pragma unroll
            for (int q = 0; q < 4; q++) acc[mt][nt][q] = 0.f;

    int r0i = tid >> 2, s0i = tid & 3;
    const float* pA0 = A  + (size_t)(row0 + r0i) * 64 + s0i * 4;
    const float* pA1 = A  + (size_t)(row0 + 64 + r0i) * 64 + s0i * 4;
    const float* pB0 = Bt + (size_t)(col0 + r0i) * 64 + s0i * 4;
    const float* pB1 = Bt + (size_t)(col0 + 64 + r0i) * 64 + s0i * 4;
    int so0 = r0i * KSTR + s0i * 4;
    int so1 = (r0i + 64) * KSTR + s0i * 4;

    *(float4*)(sm + so0)        = *(const float4*)(pA0);
    *(float4*)(sm + so1)        = *(const float4*)(pA1);
    *(float4*)(sm + MATF + so0) = *(const float4*)(pB0);
    *(float4*)(sm + MATF + so1) = *(const float4*)(pB1);
    __syncthreads();

    const int NSTAGE = 64 / KB;    // 4
    for (int ks = 0; ks < NSTAGE; ks++) {
        int buf = ks & 1;
        float4 va0, va1, vb0, vb1;
        bool more = (ks + 1 < NSTAGE);
        if (more) {
            int k0 = (ks + 1) * KB;
            va0 = *(const float4*)(pA0 + k0);
            va1 = *(const float4*)(pA1 + k0);
            vb0 = *(const float4*)(pB0 + k0);
            vb1 = *(const float4*)(pB1 + k0);
        }

        const float* Asmp = sm + buf * STAGEF + warp_m * 64 * KSTR;
        const float* Bsmp = sm + buf * STAGEF + MATF + warp_n * 32 * KSTR;

        {
            uint32_t bhf[4][2], blf[4][2];
            #pragma unroll
            for (int nt = 0; nt < 4; nt++) {
                const float* bp = Bsmp + (nt * 8 + g) * KSTR + 2 * t4;
                float2 p0 = *(const float2*)bp;
                float2 p1 = *(const float2*)(bp + 8);
                splitpair(p0.x, p0.y, bhf[nt][0], blf[nt][0]);
                splitpair(p1.x, p1.y, bhf[nt][1], blf[nt][1]);
            }
            #pragma unroll
            for (int mt = 0; mt < 4; mt++) {
                const float* ap = Asmp + (mt * 16 + g) * KSTR + 2 * t4;
                float2 q0 = *(const float2*)ap;
                float2 q1 = *(const float2*)(ap + 8 * KSTR);
                float2 q2 = *(const float2*)(ap + 8);
                float2 q3 = *(const float2*)(ap + 8 * KSTR + 8);
                uint32_t ah[4], al[4];
                splitpair(q0.x, q0.y, ah[0], al[0]);
                splitpair(q1.x, q1.y, ah[1], al[1]);
                splitpair(q2.x, q2.y, ah[2], al[2]);
                splitpair(q3.x, q3.y, ah[3], al[3]);
                #pragma unroll
                for (int nt = 0; nt < 4; nt++) mma_bf16(acc[mt][nt], ah, bhf[nt]);
                #pragma unroll
                for (int nt = 0; nt < 4; nt++) mma_bf16(acc[mt][nt], ah, blf[nt]);
                #pragma unroll
                for (int nt = 0; nt < 4; nt++) mma_bf16(acc[mt][nt], al, bhf[nt]);
            }
        }

        if (more) {
            float* nb = sm + ((ks + 1) & 1) * STAGEF;
            __syncthreads();
            *(float4*)(nb + so0)        = va0;
            *(float4*)(nb + so1)        = va1;
            *(float4*)(nb + MATF + so0) = vb0;
            *(float4*)(nb + MATF + so1) = vb1;
            __syncthreads();
        }
    }

    #pragma unroll
    for (int mt = 0; mt < 4; mt++) {
        int r0r = row0 + warp_m * 64 + mt * 16 + g;
        int r1r = r0r + 8;
        #pragma unroll
        for (int nt = 0; nt < 4; nt++) {
            int c = col0 + warp_n * 32 + nt * 8 + 2 * t4;
            *(float2*)(Sp + (size_t)r0r * 512 + c) = make_float2(acc[mt][nt][0], acc[mt][nt][1]);
            *(float2*)(Sp + (size_t)r1r * 512 + c) = make_float2(acc[mt][nt][2], acc[mt][nt][3]);
        }
    }
}

// ---------------- bf16x3 prior MLP (double-buffered, K=64) ----------------
__global__ __launch_bounds__(256, 2) void prior_mma(const float* __restrict__ bp1,
                                                    const float* __restrict__ Wp2)
{
    extern __shared__ float sm[];
    const float* A = g_k;
    const float* Bt = g_wtp;
    int tid = threadIdx.x;
    int lane = tid & 31, wid = tid >> 5;
    int g = lane >> 2, t4 = lane & 3;
    int warp_m = wid & 1;
    int warp_n = wid >> 1;
    int row0 = blockIdx.y * 128;
    int col0 = blockIdx.x * 128;

    float acc[4][4][4];
    #pragma unroll
    for (int mt = 0; mt < 4; mt++)
        #pragma unroll
        for (int nt = 0; nt < 4; nt++)
            #pragma unroll
            for (int q = 0; q < 4; q++) acc[mt][nt][q] = 0.f;

    int r0i = tid >> 2, s0i = tid & 3;
    const float* pA0 = A  + (size_t)(row0 + r0i) * 64 + s0i * 4;
    const float* pA1 = A  + (size_t)(row0 + 64 + r0i) * 64 + s0i * 4;
    const float* pB0 = Bt + (size_t)(col0 + r0i) * 64 + s0i * 4;
    const float* pB1 = Bt + (size_t)(col0 + 64 + r0i) * 64 + s0i * 4;
    int so0 = r0i * KSTR + s0i * 4;
    int so1 = (r0i + 64) * KSTR + s0i * 4;

    *(float4*)(sm + so0)        = *(const float4*)(pA0);
    *(float4*)(sm + so1)        = *(const float4*)(pA1);
    *(float4*)(sm + MATF + so0) = *(const float4*)(pB0);
    *(float4*)(sm + MATF + so1) = *(const float4*)(pB1);
    __syncthreads();

    const int NSTAGE = 64 / KB;    // 4
    for (int ks = 0; ks < NSTAGE; ks++) {
        int buf = ks & 1;
        float4 va0, va1, vb0, vb1;
        bool more = (ks + 1 < NSTAGE);
        if (more) {
            int k0 = (ks + 1) * KB;
            va0 = *(const float4*)(pA0 + k0);
            va1 = *(const float4*)(pA1 + k0);
            vb0 = *(const float4*)(pB0 + k0);
            vb1 = *(const float4*)(pB1 + k0);
        }

        const float* Asmp = sm + buf * STAGEF + warp_m * 64 * KSTR;
        const float* Bsmp = sm + buf * STAGEF + MATF + warp_n * 32 * KSTR;

        {
            uint32_t bhf[4][2], blf[4][2];
            #pragma unroll
            for (int nt = 0; nt < 4; nt++) {
                const float* bp = Bsmp + (nt * 8 + g) * KSTR + 2 * t4;
                float2 p0 = *(const float2*)bp;
                float2 p1 = *(const float2*)(bp + 8);
                splitpair(p0.x, p0.y, bhf[nt][0], blf[nt][0]);
                splitpair(p1.x, p1.y, bhf[nt][1], blf[nt][1]);
            }
            #pragma unroll
            for (int mt = 0; mt < 4; mt++) {
                const float* ap = Asmp + (mt * 16 + g) * KSTR + 2 * t4;
                float2 q0 = *(const float2*)ap;
                float2 q1 = *(const float2*)(ap + 8 * KSTR);
                float2 q2 = *(const float2*)(ap + 8);
                float2 q3 = *(const float2*)(ap + 8 * KSTR + 8);
                uint32_t ah[4], al[4];
                splitpair(q0.x, q0.y, ah[0], al[0]);
                splitpair(q1.x, q1.y, ah[1], al[1]);
                splitpair(q2.x, q2.y, ah[2], al[2]);
                splitpair(q3.x, q3.y, ah[3], al[3]);
                #pragma unroll
                for (int nt = 0; nt < 4; nt++) mma_bf16(acc[mt][nt], ah, bhf[nt]);
                #pragma unroll
                for (int nt = 0; nt < 4; nt++) mma_bf16(acc[mt][nt], ah, blf[nt]);
                #pragma unroll
                for (int nt = 0; nt < 4; nt++) mma_bf16(acc[mt][nt], al, bhf[nt]);
            }
        }

        if (more) {
            float* nb = sm + ((ks + 1) & 1) * STAGEF;
            __syncthreads();
            *(float4*)(nb + so0)        = va0;
            *(float4*)(nb + so1)        = va1;
            *(float4*)(nb + MATF + so0) = vb0;
            *(float4*)(nb + MATF + so1) = vb1;
            __syncthreads();
        }
    }

    size_t grp = (size_t)(blockIdx.x * 4 + warp_n) * NPOS;
    #pragma unroll
    for (int mt = 0; mt < 4; mt++) {
        float rs0 = 0.f, rs1 = 0.f;
        #pragma unroll
        for (int nt = 0; nt < 4; nt++) {
            int c = col0 + warp_n * 32 + nt * 8 + 2 * t4;
            float b0 = __ldg(bp1 + c), b1 = __ldg(bp1 + c + 1);
            float w0 = __ldg(Wp2 + c), w1 = __ldg(Wp2 + c + 1);
            float hv;
            hv = acc[mt][nt][0] + b0; hv = (hv >= 0.f) ? hv : 0.01f * hv; rs0 = fmaf(hv, w0, rs0);
            hv = acc[mt][nt][1] + b1; hv = (hv >= 0.f) ? hv : 0.01f * hv; rs0 = fmaf(hv, w1, rs0);
            hv = acc[mt][nt][2] + b0; hv = (hv >= 0.f) ? hv : 0.01f * hv; rs1 = fmaf(hv, w0, rs1);
            hv = acc[mt][nt][3] + b1; hv = (hv >= 0.f) ? hv : 0.01f * hv; rs1 = fmaf(hv, w1, rs1);
        }
        rs0 += __shfl_xor_sync(0xffffffffu, rs0, 1);
        rs0 += __shfl_xor_sync(0xffffffffu, rs0, 2);
        rs1 += __shfl_xor_sync(0xffffffffu, rs1, 1);
        rs1 += __shfl_xor_sync(0xffffffffu, rs1, 2);
        if (t4 == 0) {
            int r0r = row0 + warp_m * 64 + mt * 16 + g;
            g_pp[grp + r0r]     = rs0;
            g_pp[grp + r0r + 8] = rs1;
        }
    }
}

// ---------------- bf16x3 att_s @ V, cp.async 3-stage ----------------
#define VSTR 72
#define PAF 2560
#define PBF (16*VSTR)
#define PSTAGEF (PAF + PBF)
__global__ __launch_bounds__(256, 2) void pv_mma() {
    extern __shared__ float sm[];
    int bh = blockIdx.y;
    int b_ = bh >> 4, h_ = bh & 15;
    const float* A  = g_S + (size_t)bh * Ll * Ll;
    const float* Bv = g_v + (size_t)bh * Ll * DVv;
    int tid = threadIdx.x;
    int lane = tid & 31, wid = tid >> 5;
    int g = lane >> 2, t4 = lane & 3;
    int warp_m = wid & 3;
    int warp_n = wid >> 2;
    int row0 = blockIdx.x * 128;

    float acc[2][4][4];
    #pragma unroll
    for (int mt = 0; mt < 2; mt++)
        #pragma unroll
        for (int nt = 0; nt < 4; nt++)
            #pragma unroll
            for (int q = 0; q < 4; q++) acc[mt][nt][q] = 0.f;

    int r0i = tid >> 2, s0i = tid & 3;
    const float* pA0 = A + (size_t)(row0 + r0i) * 512 + s0i * 4;
    const float* pA1 = A + (size_t)(row0 + 64 + r0i) * 512 + s0i * 4;
    int rowb = tid >> 4, segb = tid & 15;
    const float* pBv = Bv + (size_t)rowb * 64 + segb * 4;
    uint32_t smb = (uint32_t)__cvta_generic_to_shared(sm);
    uint32_t ad0 = smb + (r0i * KSTR + s0i * 4) * 4;
    uint32_t ad1 = smb + ((r0i + 64) * KSTR + s0i * 4) * 4;
    uint32_t adb = smb + (PAF + rowb * VSTR + segb * 4) * 4;

    const int NSTAGE = 512 / KB;   // 32

    #pragma unroll
    for (int st = 0; st < 2; st++) {
        uint32_t b = (uint32_t)(st * PSTAGEF * 4);
        int k0 = st * KB;
        cp16(ad0 + b, pA0 + k0);
        cp16(ad1 + b, pA1 + k0);
        cp16(adb + b, pBv + (size_t)k0 * 64);
        CP_COMMIT();
    }

    for (int ks = 0; ks < NSTAGE; ks++) {
        CP_WAIT1();
        __syncthreads();
        int buf = ks % NPIPE;
        const float* Asmp = sm + buf * PSTAGEF + warp_m * 32 * KSTR;
        const float* Bsmp = sm + buf * PSTAGEF + PAF;

        {
            uint32_t bhf[4][2], blf[4][2];
            #pragma unroll
            for (int nt = 0; nt < 4; nt++) {
                int col = warp_n * 32 + nt * 8 + g;
                float b00 = Bsmp[(2 * t4) * VSTR + col];
                float b01 = Bsmp[(2 * t4 + 1) * VSTR + col];
                float b10 = Bsmp[(2 * t4 + 8) * VSTR + col];
                float b11 = Bsmp[(2 * t4 + 9) * VSTR + col];
                splitpair(b00, b01, bhf[nt][0], blf[nt][0]);
                splitpair(b10, b11, bhf[nt][1], blf[nt][1]);
            }
            #pragma unroll
            for (int mt = 0; mt < 2; mt++) {
                const float* ap = Asmp + (mt * 16 + g) * KSTR + 2 * t4;
                float2 q0 = *(const float2*)ap;
                float2 q1 = *(const float2*)(ap + 8 * KSTR);
                float2 q2 = *(const float2*)(ap + 8);
                float2 q3 = *(const float2*)(ap + 8 * KSTR + 8);
                uint32_t ah[4], al[4];
                splitpair(q0.x, q0.y, ah[0], al[0]);
                splitpair(q1.x, q1.y, ah[1], al[1]);
                splitpair(q2.x, q2.y, ah[2], al[2]);
                splitpair(q3.x, q3.y, ah[3], al[3]);
                #pragma unroll
                for (int nt = 0; nt < 4; nt++) mma_bf16(acc[mt][nt], ah, bhf[nt]);
                #pragma unroll
                for (int nt = 0; nt < 4; nt++) mma_bf16(acc[mt][nt], ah, blf[nt]);
                #pragma unroll
                for (int nt = 0; nt < 4; nt++) mma_bf16(acc[mt][nt], al, bhf[nt]);
            }
        }

        int ns = ks + 2;
        if (ns < NSTAGE) {
            uint32_t b = (uint32_t)((ns % NPIPE) * PSTAGEF * 4);
            int k0 = ns * KB;
            cp16(ad0 + b, pA0 + k0);
            cp16(ad1 + b, pA1 + k0);
            cp16(adb + b, pBv + (size_t)k0 * 64);
        }
        CP_COMMIT();
    }

    #pragma unroll
    for (int mt = 0; mt < 2; mt++) {
        int r0r = row0 + warp_m * 32 + mt * 16 + g;
        int r1r = r0r + 8;
        #pragma unroll
        for (int nt = 0; nt < 4; nt++) {
            int c = warp_n * 32 + nt * 8 + 2 * t4;
            *(float2*)(g_ao + ((size_t)b_ * Ll + r0r) * Dd + h_ * DVv + c) =
                make_float2(acc[mt][nt][0], acc[mt][nt][1]);
            *(float2*)(g_ao + ((size_t)b_ * Ll + r1r) * Dd + h_ * DVv + c) =
                make_float2(acc[mt][nt][2], acc[mt][nt][3]);
        }
    }
}

// ---------------- block reduction helper ----------------
__device__ __forceinline__ float blkred(float v, bool ismax, float* sred) {
    #pragma unroll
    for (int o = 16; o; o >>= 1) {
        float w = __shfl_xor_sync(0xffffffffu, v, o);
        v = ismax ? fmaxf(v, w) : v + w;
    }
    int wid = threadIdx.x >> 5, lid = threadIdx.x & 31;
    int nw = blockDim.x >> 5;
    if (lid == 0) sred[wid] = v;
    __syncthreads();
    if (wid == 0) {
        v = (lid < nw) ? sred[lid] : (ismax ? -3.402823e38f : 0.f);
        #pragma unroll
        for (int o = 16; o; o >>= 1) {
            float w = __shfl_xor_sync(0xffffffffu, v, o);
            v = ismax ? fmaxf(v, w) : v + w;
        }
        if (lid == 0) sred[0] = v;
    }
    __syncthreads();
    float r = sred[0];
    __syncthreads();
    return r;
}

// ---------------- fast branchless lgamma ----------------
__device__ __forceinline__ float lgamma_fast(float x) {
    bool refl = (x < 0.5f);
    float z = refl ? 1.0f - x : x;
    float p = 1.0f;
    #pragma unroll
    for (int i = 0; i < 8; i++) {
        if (z < 8.0f) { p *= z; z += 1.0f; }
    }
    float invz  = 1.0f / z;
    float invz2 = invz * invz;
    float lz = __logf(z);
    float lg = (z - 0.5f) * lz - z + 0.91893853320467274f
             + invz * (8.3333333333e-2f
             + invz2 * (-2.7777777778e-3f + 7.9365079365e-4f * invz2));
    lg -= __logf(p);
    if (refl) {
        float s = sinpif(x);
        lg = 1.1447298858494002f - __logf(fabsf(s)) - lg;
    }
    return lg;
}

// ---------------- alpha: fused 32-partial reduce + softmax + KL const terms ----------------
__global__ __launch_bounds__(512) void alpha_kernel(const float* __restrict__ bp2) {
    __shared__ float sred[32];
    int bh = blockIdx.x;
    int t = threadIdx.x;
    int i = bh * Ll + t;
    float x = 0.f;
    #pragma unroll
    for (int g2 = 0; g2 < 32; g2++) x += g_pp[(size_t)g2 * NPOS + i];
    x += bp2[0];
    float m = blkred(x, true, sred);
    float e = __expf(x - m);
    float den = blkred(e, false, sred);
    float a = e / den;
    g_alpha[i] = a;
    const float lg1 = 0.69314718f;
    const float EG  = 0.5772156649f;
    float C = a * lg1 + 2.f * EG * a + lgammaf(a + EPSF);
    float sc = blkred(C, false, sred);
    if (t == 0) atomicAdd(&g_kl, (double)(512.0f * sc));
}

// ---------------- fused row pass: warp per row (exp cached) ----------------
__global__ __launch_bounds__(256) void row_fused(const float* __restrict__ U) {
    int lane = threadIdx.x & 31;
    int wrp = threadIdx.x >> 5;
    int row = blockIdx.x * 8 + wrp;
    int bh = row >> 9;
    size_t base = (size_t)row * 512;

    float s[16];
    float m = -3.402823e38f;
    #pragma unroll
    for (int i = 0; i < 16; i++) {
        s[i] = g_S[base + lane + 32 * i];
        m = fmaxf(m, s[i]);
    }
    #pragma unroll
    for (int o = 16; o; o >>= 1) m = fmaxf(m, __shfl_xor_sync(0xffffffffu, m, o));

    float den = 0.f;
    #pragma unroll
    for (int i = 0; i < 16; i++) den += __expf(s[i] - m);
    #pragma unroll
    for (int o = 16; o; o >>= 1) den += __shfl_xor_sync(0xffffffffu, den, o);
    float logden = __logf(den);

    float t[16];
    float kl = 0.f;
    #pragma unroll
    for (int i = 0; i < 16; i++) {
        float r = s[i] - m - logden;
        float p = __expf(r);
        float lp = (r > -41.4f) ? r : __logf(p + EPSF);
        float a = g_alpha[bh * 512 + lane + 32 * i];
        kl += fmaf(-a, lp, p);
        float u = U[base + lane + 32 * i];
        float ws = u * (1.f + u * (0.5f + 0.33333333f * u));
        float wl = -__logf(1.f - u + EPSF);
        float w = (u < 0.015f) ? ws : wl;
        float gw = __logf(w + EPSF);
        t[i] = lp - lgamma_fast(3.f + 2.f * gw);
    }

    float m2 = -3.402823e38f;
    #pragma unroll
    for (int i = 0; i < 16; i++) m2 = fmaxf(m2, t[i]);
    #pragma unroll
    for (int o = 16; o; o >>= 1) m2 = fmaxf(m2, __shfl_xor_sync(0xffffffffu, m2, o));

    // compute exp once, cache in t[], then normalize
    float d2 = 0.f;
    #pragma unroll
    for (int i = 0; i < 16; i++) {
        t[i] = __expf(t[i] - m2);
        d2 += t[i];
    }
    #pragma unroll
    for (int o = 16; o; o >>= 1) d2 += __shfl_xor_sync(0xffffffffu, d2, o);
    float i2 = 1.f / d2;

    #pragma unroll
    for (int i = 0; i < 16; i++)
        g_S[base + lane + 32 * i] = t[i] * i2;

    #pragma unroll
    for (int o = 16; o; o >>= 1) kl += __shfl_xor_sync(0xffffffffu, kl, o);
    if (lane == 0) atomicAdd(&g_kl, (double)kl);
}

// ---------------- misc ----------------
__global__ void zero_kernel() { g_kl = 0.0; }

__global__ void finalize_kernel(float* out, int out_size) {
    if (out_size > Bb * Ll * Dd)
        out[Bb * Ll * Dd] = (float)(g_kl / 33554432.0);
}

// ---------------- launch ----------------
extern "C" void kernel_launch(void* const* d_in, const int* in_sizes, int n_in,
                              void* d_out, int out_size) {
    const float* queries = (const float*)d_in[0];
    const float* keys    = (const float*)d_in[1];
    const float* values  = (const float*)d_in[2];
    const float* unif    = (const float*)d_in[3];
    const float* Wq = (const float*)d_in[4];
    const float* bq = (const float*)d_in[5];
    const float* Wk = (const float*)d_in[6];
    const float* bk = (const float*)d_in[7];
    const float* Wv = (const float*)d_in[8];
    const float* bv = (const float*)d_in[9];
    const float* Wo = (const float*)d_in[10];
    const float* bo = (const float*)d_in[11];
    const float* Wp1 = (const float*)d_in[12];
    const float* bp1 = (const float*)d_in[13];
    const float* Wp2 = (const float*)d_in[14];
    const float* bp2 = (const float*)d_in[15];
    float* out = (float*)d_out;

    float *pq, *pk, *pv_;
    cudaGetSymbolAddress((void**)&pq, g_q);
    cudaGetSymbolAddress((void**)&pk, g_k);
    cudaGetSymbolAddress((void**)&pv_, g_v);

    const int GSMEM  = NPIPE * STAGEF * 4;    // 61440 B
    const int DBSMEM = 2 * STAGEF * 4;        // 40960 B
    const int PSMEM  = NPIPE * PSTAGEF * 4;   // 44544 B
    static int init_done = 0;
    static cudaStream_t s_aux;
    static cudaEvent_t ev_fork, ev_join;
    if (!init_done) {
        cudaFuncSetAttribute(qkv_mma, cudaFuncAttributeMaxDynamicSharedMemorySize, GSMEM);
        cudaFuncSetAttribute(out_mma, cudaFuncAttributeMaxDynamicSharedMemorySize, GSMEM);
        cudaFuncSetAttribute(score_mma, cudaFuncAttributeMaxDynamicSharedMemorySize, DBSMEM);
        cudaFuncSetAttribute(prior_mma, cudaFuncAttributeMaxDynamicSharedMemorySize, DBSMEM);
        cudaFuncSetAttribute(pv_mma, cudaFuncAttributeMaxDynamicSharedMemorySize, PSMEM);
        cudaStreamCreateWithFlags(&s_aux, cudaStreamNonBlocking);
        cudaEventCreateWithFlags(&ev_fork, cudaEventDisableTiming);
        cudaEventCreateWithFlags(&ev_join, cudaEventDisableTiming);
        init_done = 1;
    }

    zero_kernel<<<1, 1>>>();

    dim3 tr(32, 8);
    transpose4<<<dim3(32, 32, 4), tr>>>(Wq, Wk, Wv, Wo);
    transpose_p<<<dim3(32, 2), tr>>>(Wp1);

    qkv_mma<<<dim3(8, 32, 3), 256, GSMEM>>>(queries, keys, values, bq, bk, bv, pq, pk, pv_);

    // fork: score on aux stream, prior chain on main stream (independent)
    cudaEventRecord(ev_fork, 0);
    cudaStreamWaitEvent(s_aux, ev_fork, 0);
    score_mma<<<dim3(4, 4, BH), 256, DBSMEM, s_aux>>>();

    prior_mma<<<dim3(8, 512), 256, DBSMEM>>>(bp1, Wp2);
    alpha_kernel<<<BH, 512>>>(bp2);

    cudaEventRecord(ev_join, s_aux);
    cudaStreamWaitEvent(0, ev_join, 0);

    row_fused<<<NPOS / 8, 256>>>(unif);
    pv_mma<<<dim3(4, BH), 256, PSMEM>>>();

    out_mma<<<dim3(8, 32), 256, GSMEM>>>(bo, out);

    finalize_kernel<<<1, 1>>>(out, out_size);
}